// round 8
// baseline (speedup 1.0000x reference)
#include <cuda_runtime.h>

// ---------------------------------------------------------------------------
// MetaSR: pred[b,q] = q_feat . (h2 @ w3 + b3)
// Restructured as:
//   G[b,pix,:] = W3 @ unfold(feat)[b,:,pix]    (= 3x3 conv, 64->256 ch)
//   S[b,pix]   = b3 . unfold(feat)[b,:,pix]    (= 3x3 conv, 64->1 ch)
//   pred[b,q]  = h2[b,q,:] . G[b,pix(q),:] + S[b,pix(q)]
// h2 = relu(relu(inp@w1+b1)@w2+b2), inp = (rel_y, rel_x, r_rev)
// ---------------------------------------------------------------------------

#define BATCH 16
#define CH    64
#define HH    64
#define WW    64
#define QQ    8192
#define HID   256

// Scratch (static device globals: allocation-free per harness rules)
__device__ float g_w3T[576 * 256];                 // w3 transposed: [k][n]
__device__ float g_G[(size_t)BATCH * 4096 * HID];  // [b][pix][n], 64 MB
__device__ float g_S[BATCH * 4096];

// ---- packed f32x2 helpers (sm_103a FFMA2: 2x fp32 FMA per issue) ----------
__device__ __forceinline__ unsigned long long ffma2(unsigned long long a,
                                                    unsigned long long b,
                                                    unsigned long long c) {
    unsigned long long d;
    asm("fma.rn.f32x2 %0, %1, %2, %3;" : "=l"(d) : "l"(a), "l"(b), "l"(c));
    return d;
}
__device__ __forceinline__ unsigned long long bcast2(float v) {
    unsigned long long r;
    asm("mov.b64 %0, {%1, %1};" : "=l"(r) : "f"(v));
    return r;
}
__device__ __forceinline__ float2 unpack2(unsigned long long u) {
    float2 f;
    asm("mov.b64 {%0, %1}, %2;" : "=f"(f.x), "=f"(f.y) : "l"(u));
    return f;
}

// ---------------------------------------------------------------------------
// Kernel 0: transpose w3 [256][576] -> w3T [576][256] (one-time, tiny)
// ---------------------------------------------------------------------------
__global__ void tr_kernel(const float* __restrict__ w3) {
    int k = blockIdx.x;    // 0..575
    int n = threadIdx.x;   // 0..255
    g_w3T[k * 256 + n] = w3[n * 576 + k];
}

// ---------------------------------------------------------------------------
// Kernel 1: conv G. Grid (64 pixel-tiles, 16 batches), 256 threads.
// Tile = 8x8 pixels; thread (ty,tx): 4 pixels x 16 output channels.
// Channel set of thread tx: { tx*4 + jj*64 + e : jj in 0..3, e in 0..3 }
// (keeps LDS.128 reads contiguous across the 16 tx lanes -> conflict-free)
// ---------------------------------------------------------------------------
__global__ __launch_bounds__(256, 2)
void conv_kernel(const float* __restrict__ feat) {
    __shared__ float patch[CH * 100];                 // [c][10][10], zero-padded
    __shared__ __align__(16) float wsm[9 * 256];      // w3T rows for one input c

    const int b    = blockIdx.y;
    const int tile = blockIdx.x;
    const int ybase = (tile >> 3) << 3;
    const int xbase = (tile & 7) << 3;
    const int tid = threadIdx.x;
    const int tx = tid & 15, ty = tid >> 4;

    // Stage padded 10x10x64 input patch
    for (int idx = tid; idx < CH * 100; idx += 256) {
        int c = idx / 100, r = idx % 100;
        int py = r / 10, px = r % 10;
        int gy = ybase + py - 1, gx = xbase + px - 1;
        float v = 0.f;
        if (gy >= 0 && gy < HH && gx >= 0 && gx < WW)
            v = feat[((b * CH + c) << 12) + (gy << 6) + gx];
        patch[idx] = v;
    }

    unsigned long long acc[4][8];
#pragma unroll
    for (int i = 0; i < 4; i++)
#pragma unroll
        for (int j = 0; j < 8; j++) acc[i][j] = 0ull;

    int py_[4], px_[4];
#pragma unroll
    for (int i = 0; i < 4; i++) {
        int p = ty * 4 + i;
        py_[i] = p >> 3;
        px_[i] = p & 7;
    }

    for (int c = 0; c < CH; c++) {
        __syncthreads();  // protect wsm readers of previous c (and patch, iter 0)
#pragma unroll
        for (int i = 0; i < 9; i++)
            wsm[i * 256 + tid] = g_w3T[(c * 9 + i) * 256 + tid];
        __syncthreads();

        const float* pc = patch + c * 100;
#pragma unroll
        for (int p = 0; p < 9; p++) {
            const int di = p / 3, dj = p % 3;
            unsigned long long bb[4];
#pragma unroll
            for (int i = 0; i < 4; i++)
                bb[i] = bcast2(pc[(py_[i] + di) * 10 + px_[i] + dj]);
#pragma unroll
            for (int jj = 0; jj < 4; jj++) {
                const ulonglong2 wv = *reinterpret_cast<const ulonglong2*>(
                    &wsm[p * 256 + jj * 64 + tx * 4]);
#pragma unroll
                for (int i = 0; i < 4; i++) {
                    acc[i][jj * 2]     = ffma2(bb[i], wv.x, acc[i][jj * 2]);
                    acc[i][jj * 2 + 1] = ffma2(bb[i], wv.y, acc[i][jj * 2 + 1]);
                }
            }
        }
    }

    // Write G[b][pix][n] (float4, coalesced per jj across tx)
#pragma unroll
    for (int i = 0; i < 4; i++) {
        int gy = ybase + py_[i], gx = xbase + px_[i];
        float* gp = g_G + (size_t)(b * 4096 + (gy << 6) + gx) * HID;
#pragma unroll
        for (int jj = 0; jj < 4; jj++) {
            float2 a0 = unpack2(acc[i][jj * 2]);
            float2 a1 = unpack2(acc[i][jj * 2 + 1]);
            *reinterpret_cast<float4*>(gp + jj * 64 + tx * 4) =
                make_float4(a0.x, a0.y, a1.x, a1.y);
        }
    }
}

// ---------------------------------------------------------------------------
// Kernel 2: S[b,pix] = b3 . unfolded patch (tiny, 1 thread per pixel)
// ---------------------------------------------------------------------------
__global__ void s_kernel(const float* __restrict__ feat,
                         const float* __restrict__ b3) {
    int gid = blockIdx.x * blockDim.x + threadIdx.x;  // 0..65535
    int b = gid >> 12, pix = gid & 4095;
    int y = pix >> 6, x = pix & 63;
    float acc = 0.f;
    for (int c = 0; c < CH; c++) {
        const float* fb = feat + ((b * CH + c) << 12);
#pragma unroll
        for (int di = 0; di < 3; di++) {
            int gy = y + di - 1;
            if (gy < 0 || gy >= HH) continue;
#pragma unroll
            for (int dj = 0; dj < 3; dj++) {
                int gx = x + dj - 1;
                if (gx < 0 || gx >= WW) continue;
                acc = fmaf(__ldg(&b3[c * 9 + di * 3 + dj]), fb[(gy << 6) + gx], acc);
            }
        }
    }
    g_S[gid] = acc;
}

// ---------------------------------------------------------------------------
// Kernel 3: queries. Grid 2048 blocks x 256 threads; 64 queries per block.
// Thread (ty,tx): 4 queries x 16 hidden channels of h2; K=256 chunked by 32.
// h1 is recomputed per K-chunk (3 FMAs/element) so everything fits in 48 KB.
// ---------------------------------------------------------------------------
__global__ __launch_bounds__(256, 2)
void query_kernel(const float* __restrict__ coord, const float* __restrict__ cell,
                  const float* __restrict__ w1, const float* __restrict__ b1,
                  const float* __restrict__ w2, const float* __restrict__ b2,
                  float* __restrict__ out) {
    __shared__ float h1c[64 * 33];                 // h1 chunk [q][kk], padded
    __shared__ __align__(16) float wsm[32 * 256];  // w2 chunk [kk][n]
    __shared__ float sIn[64 * 3];                  // (rel_y, rel_x, r_rev)
    __shared__ int   sPix[64];

    const int tid = threadIdx.x;
    const int tx = tid & 15, ty = tid >> 4;
    const int b = blockIdx.x >> 7;                 // 128 blocks per batch
    const int qbase = (blockIdx.x & 127) << 6;

    if (tid < 64) {
        const int qg = b * QQ + qbase + tid;
        const float2 co = *reinterpret_cast<const float2*>(coord + 2 * qg);
        const float2 cl = *reinterpret_cast<const float2*>(cell + 2 * qg);
        // coord_ = coord - cell/2   (exact op order, no FMA contraction)
        float cm0 = __fsub_rn(co.x, __fmul_rn(cl.x, 0.5f));
        float cm1 = __fsub_rn(co.y, __fmul_rn(cl.y, 0.5f));
        const float EPS = 1e-6f;
        const float LO = (float)(-1.0 + 1e-6);
        const float HI = (float)(1.0 - 1e-6);
        float cq0 = fminf(fmaxf(__fadd_rn(cm0, EPS), LO), HI);
        float cq1 = fminf(fmaxf(__fadd_rn(cm1, EPS), LO), HI);
        // t = ((cq+1)*64 - 1)/2 ; idx = clip(round_half_even(t), 0, 63)
        float t0 = __fmul_rn(__fsub_rn(__fmul_rn(__fadd_rn(cq0, 1.0f), 64.0f), 1.0f), 0.5f);
        float t1 = __fmul_rn(__fsub_rn(__fmul_rn(__fadd_rn(cq1, 1.0f), 64.0f), 1.0f), 0.5f);
        float r0 = fminf(fmaxf(rintf(t0), 0.f), 63.f);
        float r1 = fminf(fmaxf(rintf(t1), 0.f), 63.f);
        int iy = (int)r0, ix = (int)r1;
        float qy = __fsub_rn(__fmul_rn(r0, 0.03125f), 1.0f);  // 2i/64 - 1 (exact)
        float qx = __fsub_rn(__fmul_rn(r1, 0.03125f), 1.0f);
        sIn[tid * 3 + 0] = __fmul_rn(__fsub_rn(cm0, qy), 32.f);
        sIn[tid * 3 + 1] = __fmul_rn(__fsub_rn(cm1, qx), 32.f);
        sIn[tid * 3 + 2] = __fmul_rn(cl.x, 32.f);
        sPix[tid] = (iy << 6) + ix;
    }

    unsigned long long acc[4][8];
#pragma unroll
    for (int i = 0; i < 4; i++)
#pragma unroll
        for (int j = 0; j < 8; j++) acc[i][j] = 0ull;

    for (int k0 = 0; k0 < HID; k0 += 32) {
        __syncthreads();  // sIn ready (iter 0); prior readers of h1c/wsm done
        // Build h1 chunk: h1c[q][kk] = relu(inp_q . w1[:,k] + b1[k])
#pragma unroll
        for (int e = tid; e < 64 * 32; e += 256) {
            int q = e >> 5, kk = e & 31;
            int k = k0 + kk;
            float h = b1[k];
            h = fmaf(sIn[q * 3 + 0], w1[k], h);
            h = fmaf(sIn[q * 3 + 1], w1[256 + k], h);
            h = fmaf(sIn[q * 3 + 2], w1[512 + k], h);
            h1c[q * 33 + kk] = fmaxf(h, 0.f);
        }
        // Load w2 chunk [32][256]
        {
            const float4* src = reinterpret_cast<const float4*>(w2 + k0 * 256);
            float4* dst = reinterpret_cast<float4*>(wsm);
#pragma unroll
            for (int i = 0; i < 8; i++) dst[i * 256 + tid] = src[i * 256 + tid];
        }
        __syncthreads();

#pragma unroll 4
        for (int kk = 0; kk < 32; kk++) {
            unsigned long long bb[4];
#pragma unroll
            for (int i = 0; i < 4; i++)
                bb[i] = bcast2(h1c[(ty * 4 + i) * 33 + kk]);
#pragma unroll
            for (int jj = 0; jj < 4; jj++) {
                const ulonglong2 wv = *reinterpret_cast<const ulonglong2*>(
                    &wsm[kk * 256 + jj * 64 + tx * 4]);
#pragma unroll
                for (int i = 0; i < 4; i++) {
                    acc[i][jj * 2]     = ffma2(bb[i], wv.x, acc[i][jj * 2]);
                    acc[i][jj * 2 + 1] = ffma2(bb[i], wv.y, acc[i][jj * 2 + 1]);
                }
            }
        }
    }

    // Epilogue: h2 = relu(acc + b2); dot with G[b,pix,:]; reduce over tx
    float dot[4] = {0.f, 0.f, 0.f, 0.f};
    const float* Gb = g_G + (size_t)b * 4096 * HID;
#pragma unroll
    for (int i = 0; i < 4; i++) {
        const int pix = sPix[ty * 4 + i];
        const float* gp = Gb + (size_t)pix * HID;
#pragma unroll
        for (int jj = 0; jj < 4; jj++) {
            float4 bv = *reinterpret_cast<const float4*>(b2 + jj * 64 + tx * 4);
            float4 gv = *reinterpret_cast<const float4*>(gp + jj * 64 + tx * 4);
            float2 a0 = unpack2(acc[i][jj * 2]);
            float2 a1 = unpack2(acc[i][jj * 2 + 1]);
            float h0 = fmaxf(a0.x + bv.x, 0.f);
            float h1v = fmaxf(a0.y + bv.y, 0.f);
            float h2v = fmaxf(a1.x + bv.z, 0.f);
            float h3 = fmaxf(a1.y + bv.w, 0.f);
            dot[i] = fmaf(h0, gv.x, dot[i]);
            dot[i] = fmaf(h1v, gv.y, dot[i]);
            dot[i] = fmaf(h2v, gv.z, dot[i]);
            dot[i] = fmaf(h3, gv.w, dot[i]);
        }
    }
#pragma unroll
    for (int i = 0; i < 4; i++) {
#pragma unroll
        for (int off = 8; off >= 1; off >>= 1)
            dot[i] += __shfl_down_sync(0xffffffffu, dot[i], off, 16);
    }
    if (tx == 0) {
#pragma unroll
        for (int i = 0; i < 4; i++) {
            const int qloc = ty * 4 + i;
            out[b * QQ + qbase + qloc] = dot[i] + g_S[b * 4096 + sPix[qloc]];
        }
    }
}

// ---------------------------------------------------------------------------
extern "C" void kernel_launch(void* const* d_in, const int* in_sizes, int n_in,
                              void* d_out, int out_size) {
    const float* feat  = (const float*)d_in[0];
    const float* coord = (const float*)d_in[1];
    const float* cell  = (const float*)d_in[2];
    const float* w1    = (const float*)d_in[3];
    const float* b1    = (const float*)d_in[4];
    const float* w2    = (const float*)d_in[5];
    const float* b2    = (const float*)d_in[6];
    const float* w3    = (const float*)d_in[7];
    const float* b3    = (const float*)d_in[8];
    float* out = (float*)d_out;

    tr_kernel<<<576, 256>>>(w3);
    conv_kernel<<<dim3(64, 16), 256>>>(feat);
    s_kernel<<<256, 256>>>(feat, b3);
    query_kernel<<<2048, 256>>>(coord, cell, w1, b1, w2, b2, out);
}

// round 13
// speedup vs baseline: 1.0771x; 1.0771x over previous
#include <cuda_runtime.h>

// ---------------------------------------------------------------------------
// MetaSR restructured:
//   G[b,pix,:] = W3 @ unfold(feat)[b,:,pix]    (= 3x3 conv, 64->256 ch)
//   S[b,pix]   = b3 . unfold(feat)[b,:,pix]    (fused into conv kernel)
//   pred[b,q]  = h2[b,q,:] . G[b,pix(q),:] + S[b,pix(q)]
// h2 = relu(relu(inp@w1+b1)@w2+b2), inp = (rel_y, rel_x, r_rev)
// ---------------------------------------------------------------------------

#define BATCH 16
#define CH    64
#define HH    64
#define WW    64
#define QQ    8192
#define HID   256

__device__ float g_w3T[576 * 256];                 // w3 transposed: [k][n]
__device__ float g_G[(size_t)BATCH * 4096 * HID];  // [b][pix][n], 64 MB
__device__ float g_S[BATCH * 4096];

// ---- packed f32x2 helpers --------------------------------------------------
__device__ __forceinline__ unsigned long long ffma2(unsigned long long a,
                                                    unsigned long long b,
                                                    unsigned long long c) {
    unsigned long long d;
    asm("fma.rn.f32x2 %0, %1, %2, %3;" : "=l"(d) : "l"(a), "l"(b), "l"(c));
    return d;
}
__device__ __forceinline__ unsigned long long bcast2(float v) {
    unsigned long long r;
    asm("mov.b64 %0, {%1, %1};" : "=l"(r) : "f"(v));
    return r;
}
__device__ __forceinline__ float2 unpack2(unsigned long long u) {
    float2 f;
    asm("mov.b64 {%0, %1}, %2;" : "=f"(f.x), "=f"(f.y) : "l"(u));
    return f;
}

// ---------------------------------------------------------------------------
// Kernel 0: transpose w3 [256][576] -> w3T [576][256]
// ---------------------------------------------------------------------------
__global__ void tr_kernel(const float* __restrict__ w3) {
    int k = blockIdx.x;
    int n = threadIdx.x;
    g_w3T[k * 256 + n] = w3[n * 576 + k];
}

// ---------------------------------------------------------------------------
// Kernel 1: conv G (+ fused S). Grid (64 tiles, 16 batches), 256 threads.
// Thread (ty,tx): 4 pixels x 16 contiguous channels (ch = tx*16 + slot*4).
// Weight loads use a per-lane slot rotation so the four LDS.128 per step
// spread across all four 4-bank groups (2 wavefronts/instr instead of 8).
// Weights double-buffered: 1 barrier per input channel.
// ---------------------------------------------------------------------------
__global__ __launch_bounds__(256, 2)
void conv_kernel(const float* __restrict__ feat, const float* __restrict__ b3) {
    __shared__ float patch[CH * 100];                   // [c][10][10], zero-padded
    __shared__ __align__(16) float wbuf[2][9 * 256];    // ping-pong w3T rows
    __shared__ float sS[4 * 64];                        // fused-S partials

    const int b    = blockIdx.y;
    const int tile = blockIdx.x;
    const int ybase = (tile >> 3) << 3;
    const int xbase = (tile & 7) << 3;
    const int tid = threadIdx.x;
    const int tx = tid & 15, ty = tid >> 4;
    const int ro = (tid >> 1) & 3;                      // lane-constant rotation

    int chOff[4];
#pragma unroll
    for (int jj = 0; jj < 4; jj++)
        chOff[jj] = tx * 16 + ((jj + ro) & 3) * 4;      // slot jj's channel base

    // Stage padded 10x10x64 input patch
    for (int idx = tid; idx < CH * 100; idx += 256) {
        int c = idx / 100, r = idx % 100;
        int py = r / 10, px = r % 10;
        int gy = ybase + py - 1, gx = xbase + px - 1;
        float v = 0.f;
        if (gy >= 0 && gy < HH && gx >= 0 && gx < WW)
            v = feat[((b * CH + c) << 12) + (gy << 6) + gx];
        patch[idx] = v;
    }
    // Stage weights for c=0
#pragma unroll
    for (int i = 0; i < 9; i++)
        wbuf[0][i * 256 + tid] = g_w3T[i * 256 + tid];
    __syncthreads();

    // Fused S partials: 4 groups of 64 threads, 16 channels each
    {
        int pp = tid & 63, grp = tid >> 6;
        int spy = pp >> 3, spx = pp & 7;
        float s = 0.f;
        for (int c = grp * 16; c < grp * 16 + 16; c++) {
            const float* pc = patch + c * 100;
#pragma unroll
            for (int di = 0; di < 3; di++)
#pragma unroll
                for (int dj = 0; dj < 3; dj++)
                    s = fmaf(__ldg(&b3[c * 9 + di * 3 + dj]),
                             pc[(spy + di) * 10 + spx + dj], s);
        }
        sS[grp * 64 + pp] = s;
    }

    unsigned long long acc[4][8];
#pragma unroll
    for (int i = 0; i < 4; i++)
#pragma unroll
        for (int j = 0; j < 8; j++) acc[i][j] = 0ull;

    int py_[4], px_[4];
#pragma unroll
    for (int i = 0; i < 4; i++) {
        int p = ty * 4 + i;
        py_[i] = p >> 3;
        px_[i] = p & 7;
    }

    for (int c = 0; c < CH; c++) {
        const float* wcur = wbuf[c & 1];
        // Prefetch next channel's weights into the other buffer
        if (c + 1 < CH) {
            float* wnxt = wbuf[(c + 1) & 1];
#pragma unroll
            for (int i = 0; i < 9; i++)
                wnxt[i * 256 + tid] = g_w3T[((c + 1) * 9 + i) * 256 + tid];
        }
        const float* pc = patch + c * 100;
#pragma unroll
        for (int pos = 0; pos < 9; pos++) {
            const int di = pos / 3, dj = pos % 3;
            unsigned long long bb[4];
#pragma unroll
            for (int i = 0; i < 4; i++)
                bb[i] = bcast2(pc[(py_[i] + di) * 10 + px_[i] + dj]);
#pragma unroll
            for (int jj = 0; jj < 4; jj++) {
                const ulonglong2 wv = *reinterpret_cast<const ulonglong2*>(
                    &wcur[pos * 256 + chOff[jj]]);
#pragma unroll
                for (int i = 0; i < 4; i++) {
                    acc[i][jj * 2]     = ffma2(bb[i], wv.x, acc[i][jj * 2]);
                    acc[i][jj * 2 + 1] = ffma2(bb[i], wv.y, acc[i][jj * 2 + 1]);
                }
            }
        }
        __syncthreads();  // readers of wcur done before it is overwritten
    }

    // Write G[b][pix][ch]
#pragma unroll
    for (int i = 0; i < 4; i++) {
        int gy = ybase + py_[i], gx = xbase + px_[i];
        float* gp = g_G + (size_t)(b * 4096 + (gy << 6) + gx) * HID;
#pragma unroll
        for (int jj = 0; jj < 4; jj++) {
            float2 a0 = unpack2(acc[i][jj * 2]);
            float2 a1 = unpack2(acc[i][jj * 2 + 1]);
            *reinterpret_cast<float4*>(gp + chOff[jj]) =
                make_float4(a0.x, a0.y, a1.x, a1.y);
        }
    }

    // Reduce + write S (sS writes ordered by the mainloop barriers)
    if (tid < 64) {
        float s = sS[tid] + sS[64 + tid] + sS[128 + tid] + sS[192 + tid];
        int gy = ybase + (tid >> 3), gx = xbase + (tid & 7);
        g_S[b * 4096 + (gy << 6) + gx] = s;
    }
}

// ---------------------------------------------------------------------------
// Kernel 2: queries. 2048 blocks x 256 threads; 64 queries/block.
// Thread (ty,tx): 4 queries x 16 contiguous channels, same rotation trick.
// ---------------------------------------------------------------------------
__global__ __launch_bounds__(256, 2)
void query_kernel(const float* __restrict__ coord, const float* __restrict__ cell,
                  const float* __restrict__ w1, const float* __restrict__ b1,
                  const float* __restrict__ w2, const float* __restrict__ b2,
                  float* __restrict__ out) {
    __shared__ float h1c[64 * 33];                 // h1 chunk [q][kk]
    __shared__ __align__(16) float wsm[32 * 256];  // w2 chunk [kk][n]
    __shared__ float sIn[64 * 3];
    __shared__ int   sPix[64];

    const int tid = threadIdx.x;
    const int tx = tid & 15, ty = tid >> 4;
    const int ro = (tid >> 1) & 3;
    const int b = blockIdx.x >> 7;
    const int qbase = (blockIdx.x & 127) << 6;

    int chOff[4];
#pragma unroll
    for (int jj = 0; jj < 4; jj++)
        chOff[jj] = tx * 16 + ((jj + ro) & 3) * 4;

    if (tid < 64) {
        const int qg = b * QQ + qbase + tid;
        const float2 co = *reinterpret_cast<const float2*>(coord + 2 * qg);
        const float2 cl = *reinterpret_cast<const float2*>(cell + 2 * qg);
        float cm0 = __fsub_rn(co.x, __fmul_rn(cl.x, 0.5f));
        float cm1 = __fsub_rn(co.y, __fmul_rn(cl.y, 0.5f));
        const float EPS = 1e-6f;
        const float LO = (float)(-1.0 + 1e-6);
        const float HI = (float)(1.0 - 1e-6);
        float cq0 = fminf(fmaxf(__fadd_rn(cm0, EPS), LO), HI);
        float cq1 = fminf(fmaxf(__fadd_rn(cm1, EPS), LO), HI);
        float t0 = __fmul_rn(__fsub_rn(__fmul_rn(__fadd_rn(cq0, 1.0f), 64.0f), 1.0f), 0.5f);
        float t1 = __fmul_rn(__fsub_rn(__fmul_rn(__fadd_rn(cq1, 1.0f), 64.0f), 1.0f), 0.5f);
        float r0 = fminf(fmaxf(rintf(t0), 0.f), 63.f);
        float r1 = fminf(fmaxf(rintf(t1), 0.f), 63.f);
        int iy = (int)r0, ix = (int)r1;
        float qy = __fsub_rn(__fmul_rn(r0, 0.03125f), 1.0f);
        float qx = __fsub_rn(__fmul_rn(r1, 0.03125f), 1.0f);
        sIn[tid * 3 + 0] = __fmul_rn(__fsub_rn(cm0, qy), 32.f);
        sIn[tid * 3 + 1] = __fmul_rn(__fsub_rn(cm1, qx), 32.f);
        sIn[tid * 3 + 2] = __fmul_rn(cl.x, 32.f);
        sPix[tid] = (iy << 6) + ix;
    }

    unsigned long long acc[4][8];
#pragma unroll
    for (int i = 0; i < 4; i++)
#pragma unroll
        for (int j = 0; j < 8; j++) acc[i][j] = 0ull;

    for (int k0 = 0; k0 < HID; k0 += 32) {
        __syncthreads();
        // h1 chunk: h1c[q][kk] = relu(inp_q . w1[:,k] + b1[k])
#pragma unroll
        for (int e = tid; e < 64 * 32; e += 256) {
            int q = e >> 5, kk = e & 31;
            int k = k0 + kk;
            float h = b1[k];
            h = fmaf(sIn[q * 3 + 0], w1[k], h);
            h = fmaf(sIn[q * 3 + 1], w1[256 + k], h);
            h = fmaf(sIn[q * 3 + 2], w1[512 + k], h);
            h1c[q * 33 + kk] = fmaxf(h, 0.f);
        }
        // w2 chunk [32][256]
        {
            const float4* src = reinterpret_cast<const float4*>(w2 + k0 * 256);
            float4* dst = reinterpret_cast<float4*>(wsm);
#pragma unroll
            for (int i = 0; i < 8; i++) dst[i * 256 + tid] = src[i * 256 + tid];
        }
        __syncthreads();

#pragma unroll 4
        for (int kk = 0; kk < 32; kk++) {
            unsigned long long bb[4];
#pragma unroll
            for (int i = 0; i < 4; i++)
                bb[i] = bcast2(h1c[(ty * 4 + i) * 33 + kk]);
#pragma unroll
            for (int jj = 0; jj < 4; jj++) {
                const ulonglong2 wv = *reinterpret_cast<const ulonglong2*>(
                    &wsm[kk * 256 + chOff[jj]]);
#pragma unroll
                for (int i = 0; i < 4; i++) {
                    acc[i][jj * 2]     = ffma2(bb[i], wv.x, acc[i][jj * 2]);
                    acc[i][jj * 2 + 1] = ffma2(bb[i], wv.y, acc[i][jj * 2 + 1]);
                }
            }
        }
    }

    // Epilogue: h2 = relu(acc + b2); dot with G[b,pix,:]; reduce over tx
    float dot[4] = {0.f, 0.f, 0.f, 0.f};
    const float* Gb = g_G + (size_t)b * 4096 * HID;
#pragma unroll
    for (int i = 0; i < 4; i++) {
        const int pix = sPix[ty * 4 + i];
        const float* gp = Gb + (size_t)pix * HID;
#pragma unroll
        for (int jj = 0; jj < 4; jj++) {
            float4 bv = *reinterpret_cast<const float4*>(b2 + chOff[jj]);
            float4 gv = *reinterpret_cast<const float4*>(gp + chOff[jj]);
            float2 a0 = unpack2(acc[i][jj * 2]);
            float2 a1 = unpack2(acc[i][jj * 2 + 1]);
            float h0  = fmaxf(a0.x + bv.x, 0.f);
            float h1v = fmaxf(a0.y + bv.y, 0.f);
            float h2v = fmaxf(a1.x + bv.z, 0.f);
            float h3  = fmaxf(a1.y + bv.w, 0.f);
            dot[i] = fmaf(h0, gv.x, dot[i]);
            dot[i] = fmaf(h1v, gv.y, dot[i]);
            dot[i] = fmaf(h2v, gv.z, dot[i]);
            dot[i] = fmaf(h3, gv.w, dot[i]);
        }
    }
#pragma unroll
    for (int i = 0; i < 4; i++) {
#pragma unroll
        for (int off = 8; off >= 1; off >>= 1)
            dot[i] += __shfl_down_sync(0xffffffffu, dot[i], off, 16);
    }
    if (tx == 0) {
#pragma unroll
        for (int i = 0; i < 4; i++) {
            const int qloc = ty * 4 + i;
            out[b * QQ + qbase + qloc] = dot[i] + g_S[b * 4096 + sPix[qloc]];
        }
    }
}

// ---------------------------------------------------------------------------
extern "C" void kernel_launch(void* const* d_in, const int* in_sizes, int n_in,
                              void* d_out, int out_size) {
    const float* feat  = (const float*)d_in[0];
    const float* coord = (const float*)d_in[1];
    const float* cell  = (const float*)d_in[2];
    const float* w1    = (const float*)d_in[3];
    const float* b1    = (const float*)d_in[4];
    const float* w2    = (const float*)d_in[5];
    const float* b2    = (const float*)d_in[6];
    const float* w3    = (const float*)d_in[7];
    const float* b3    = (const float*)d_in[8];
    float* out = (float*)d_out;

    tr_kernel<<<576, 256>>>(w3);
    conv_kernel<<<dim3(64, 16), 256>>>(feat, b3);
    query_kernel<<<2048, 256>>>(coord, cell, w1, b1, w2, b2, out);
}